// round 5
// baseline (speedup 1.0000x reference)
#include <cuda_runtime.h>

// Fixed problem shape
#define GX 432
#define GY 496
#define NVOX (GX * GY)            // 214272 (GZ = 1)
#define MAXV 160000
#define NPER 200000
#define NPTS (4 * NPER)           // 800000
#define SBLK 148                  // scan blocks == SM count (single wave)
#define STPB 1024                 // 32 warps
#define NWARP (SBLK * 32)         // 4736 global warps; 3348 carry voxels

__device__ int      g_count[NVOX];   // zero-initialized at load; kernel restores
__device__ float4   g_sum[NVOX];     // the zero state after consuming it
__device__ int      g_bsum[SBLK];
__device__ unsigned g_bar;

// ---------------------------------------------------------------------------
// Per-point scatter: 4 points/thread, float4 plane loads, 2 RED msgs/point
// ---------------------------------------------------------------------------
__global__ void __launch_bounds__(256)
accum_kernel(const float* __restrict__ clouds) {
    int t = blockIdx.x * 256 + threadIdx.x;     // one thread = 4 points
    if (t >= NPTS / 4) return;
    int b = t / (NPER / 4);
    int i = t - b * (NPER / 4);
    const float* base = clouds + (size_t)b * 4 * NPER;
    float4 x4 = ((const float4*)(base))[i];
    float4 y4 = ((const float4*)(base + NPER))[i];
    float4 z4 = ((const float4*)(base + 2 * NPER))[i];
    float4 w4 = ((const float4*)(base + 3 * NPER))[i];

    float xs[4] = {x4.x, x4.y, x4.z, x4.w};
    float ys[4] = {y4.x, y4.y, y4.z, y4.w};
    float zs[4] = {z4.x, z4.y, z4.z, z4.w};
    float ws[4] = {w4.x, w4.y, w4.z, w4.w};

#pragma unroll
    for (int k = 0; k < 4; k++) {
        // IEEE divides: bit-exact voxel assignment vs XLA (immune to fast_math)
        int cx = (int)floorf(__fdiv_rn(xs[k],          0.16f));
        int cy = (int)floorf(__fdiv_rn(ys[k] + 39.68f, 0.16f));
        int cz = (int)floorf(__fdiv_rn(zs[k] + 3.0f,   4.0f));
        if (cx < 0 || cx >= GX || cy < 0 || cy >= GY || cz != 0) continue;
        int lin = cy * GX + cx;
        atomicAdd(&g_count[lin], 1);                     // RED.E.ADD
        asm volatile("red.global.add.v4.f32 [%0], {%1, %2, %3, %4};"
                     :: "l"(&g_sum[lin].x),
                        "f"(xs[k]), "f"(ys[k]), "f"(zs[k]), "f"(ws[k])
                     : "memory");
    }
}

// ---------------------------------------------------------------------------
// Compaction: ALL heavy work (mean compute + re-zero) BEFORE the barrier;
// only the rank-offset store after. 148 blocks x 1024 threads.
// ---------------------------------------------------------------------------
__global__ void __launch_bounds__(STPB)
scanemit_kernel(float4* __restrict__ out) {
    const int tid  = threadIdx.x;
    const int blk  = blockIdx.x;
    const int wid  = tid >> 5;
    const int lane = tid & 31;
    const unsigned lt = (1u << lane) - 1u;
    const int wbase = (blk * 32 + wid) * 64;   // 64 voxels per global warp

    __shared__ int s_wsum[32];
    __shared__ int s_woff[32];
    __shared__ int s_prefix, s_total;

    const float4 fz = make_float4(0.f, 0.f, 0.f, 0.f);

    // ---- load counts (coalesced), ballot occupancy ----
    const int v0 = wbase + lane;
    const int v1 = wbase + 32 + lane;
    int c0 = (v0 < NVOX) ? g_count[v0] : 0;
    int c1 = (v1 < NVOX) ? g_count[v1] : 0;
    unsigned b0 = __ballot_sync(0xFFFFFFFFu, c0 > 0);
    unsigned b1 = __ballot_sync(0xFFFFFFFFu, c1 > 0);

    // ---- compute means NOW (g_sum is stable: produced by previous launch);
    //      re-zero scratch for the next graph replay ----
    float4 m0 = fz, m1 = fz;
    if (c0 > 0) {
        float c = (float)c0;
        float4 s = g_sum[v0];
        m0 = make_float4(__fdiv_rn(s.x, c), __fdiv_rn(s.y, c),
                         __fdiv_rn(s.z, c), __fdiv_rn(s.w, c));
        g_sum[v0] = fz;
        g_count[v0] = 0;
    }
    if (c1 > 0) {
        float c = (float)c1;
        float4 s = g_sum[v1];
        m1 = make_float4(__fdiv_rn(s.x, c), __fdiv_rn(s.y, c),
                         __fdiv_rn(s.z, c), __fdiv_rn(s.w, c));
        g_sum[v1] = fz;
        g_count[v1] = 0;
    }

    if (lane == 0) s_wsum[wid] = __popc(b0) + __popc(b1);
    __syncthreads();

    // ---- warp 0: exclusive scan of 32 warp sums; publish block total ----
    if (wid == 0) {
        int v = s_wsum[lane];
        int s = v;
        #pragma unroll
        for (int off = 1; off < 32; off <<= 1) {
            int t = __shfl_up_sync(0xFFFFFFFFu, s, off);
            if (lane >= off) s += t;
        }
        s_woff[lane] = s - v;
        if (lane == 31) {
            g_bsum[blk] = s;
            __threadfence();                 // publish before barrier arrive
        }
    }

    // ---- grid barrier (ticket; wrap-safe across graph replays) ----
    __syncthreads();
    if (tid == 0) {
        __threadfence();
        unsigned t = atomicAdd(&g_bar, 1u);
        unsigned base = t - (t % SBLK);
        while (*(volatile unsigned*)&g_bar - base < SBLK) { }
        __threadfence();
    }
    __syncthreads();

    // ---- warp 0: redundant scan of the 148 block totals ----
    if (wid == 0) {
        int carry = 0;
        #pragma unroll
        for (int i = 0; i < 5; i++) {
            int idx = i * 32 + lane;
            int v = (idx < SBLK) ? g_bsum[idx] : 0;
            int s = v;
            #pragma unroll
            for (int off = 1; off < 32; off <<= 1) {
                int t = __shfl_up_sync(0xFFFFFFFFu, s, off);
                if (lane >= off) s += t;
            }
            if (idx == blk)      s_prefix = carry + s - v;
            if (idx == SBLK - 1) s_total  = carry + s;
            carry += __shfl_sync(0xFFFFFFFFu, s, 31);
        }
    }
    __syncthreads();

    // ---- only the stores remain after the barrier ----
    int wrank = s_prefix + s_woff[wid];
    if (c0 > 0) {
        int r = wrank + __popc(b0 & lt);
        if (r < MAXV) out[r] = m0;
    }
    wrank += __popc(b0);
    if (c1 > 0) {
        int r = wrank + __popc(b1 & lt);
        if (r < MAXV) out[r] = m1;
    }

    // ---- zero any unwritten output rows (never in practice: ~209k occupied) -
    for (int r = s_total + blk * STPB + tid; r < MAXV; r += SBLK * STPB)
        out[r] = fz;
}

// ---------------------------------------------------------------------------
extern "C" void kernel_launch(void* const* d_in, const int* in_sizes, int n_in,
                              void* d_out, int out_size) {
    const float* clouds = (const float*)d_in[0];
    float4* out = (float4*)d_out;
    accum_kernel<<<(NPTS / 4 + 255) / 256, 256>>>(clouds);
    scanemit_kernel<<<SBLK, STPB>>>(out);
}